// round 15
// baseline (speedup 1.0000x reference)
#include <cuda_runtime.h>
#include <cuda_bf16.h>
#include <cuda_fp16.h>
#include <cstdint>
#include <math.h>

// Problem constants
#define BB 2
#define LL 2048
#define DD 1024
#define HH 16
#define DHH 64
#define TT (BB*LL)          // 4096 tokens
#define EPS 1e-5f
#define NBH (BB*HH)         // 32
#define KW 512              // k-pair words per row (GK/2)

// -------- scratch (device globals: allocation-free rule) --------
__device__ float g_qkv[TT * 3 * DD];      // QKV GEMM output (fp32, LN needs it)
__device__ float2 g_cs[LL * 32];          // RoPE cos/sin table [l][fi]
// fp16 operand planes for projection GEMMs (half2 k-pair words)
__device__ __align__(16) uint32_t g_hh[TT * KW];        // LN1 out, fp16
__device__ __align__(16) uint32_t g_wqkv16[3 * DD * KW];
__device__ __align__(16) uint32_t g_outw16[DD * KW];
__device__ __align__(16) uint32_t g_ctx16[TT * KW];     // attention out, fp16
// fp16 Q/K planes, word = half2 of adjacent head-dims: [bh][l][32 words]
__device__ __align__(16) uint32_t g_qf[NBH * LL * 32];
__device__ __align__(16) uint32_t g_kf[NBH * LL * 32];
// fp16 transposed V tiles: [bh][kt(32)][d(64)][32 l-pair words]
__device__ __align__(16) uint32_t g_vtf[NBH * 32 * 64 * 32];

__device__ __forceinline__ uint32_t h2pack(float a, float b) {
    __half2 t = __floats2half2_rn(a, b);
    return *reinterpret_cast<uint32_t*>(&t);
}
// fp16 m16n8k16 (all tensor paths)
__device__ __forceinline__ void mma16816h(float* c, uint32_t a0, uint32_t a1,
                                          uint32_t a2, uint32_t a3,
                                          uint32_t b0, uint32_t b1) {
    asm volatile(
        "mma.sync.aligned.m16n8k16.row.col.f32.f16.f16.f32 "
        "{%0,%1,%2,%3}, {%4,%5,%6,%7}, {%8,%9}, {%0,%1,%2,%3};"
        : "+f"(c[0]), "+f"(c[1]), "+f"(c[2]), "+f"(c[3])
        : "r"(a0), "r"(a1), "r"(a2), "r"(a3), "r"(b0), "r"(b1));
}

__device__ __forceinline__ void cp16(uint32_t dst, const void* src) {
    asm volatile("cp.async.ca.shared.global [%0], [%1], 16;"
                 :: "r"(dst), "l"(src));
}
__device__ __forceinline__ void cp_commit() {
    asm volatile("cp.async.commit_group;");
}
__device__ __forceinline__ void cp_wait_all() {
    asm volatile("cp.async.wait_all;" ::: "memory");
}

// ---------------- fp32 -> fp16-words conversion ----------------
__global__ void cvt16_kernel(const float* __restrict__ in,
                             uint32_t* __restrict__ out, int nwords) {
    int i = blockIdx.x * 256 + threadIdx.x;
    if (i < nwords) {
        float2 v = ((const float2*)in)[i];
        out[i] = h2pack(v.x, v.y);
    }
}

// ===================== fp16 GEMM, cp.async 3-stage pipeline ==========
#define NCHUNK 32            // 1024 / 32
#define PADh 20              // 16 k-pair words + 4 pad
#define STGW (2 * 128 * PADh)        // words per stage (A+B)
#define GEMM_SMEM (3 * STGW * 4)     // 61440 B

__global__ __launch_bounds__(256)
void gemm_mma_fp16(const uint32_t* __restrict__ A, const uint32_t* __restrict__ B,
                   float* __restrict__ C, int N) {
    extern __shared__ uint32_t smg[];

    const int tid = threadIdx.x;
    const int wid = tid >> 5, lane = tid & 31;
    const int grp = lane >> 2, qd = lane & 3;
    const int wm = wid >> 1, wn = wid & 1;
    const int m0 = blockIdx.y * 128;
    const int n0 = blockIdx.x * 128;

    const uint32_t sb = (uint32_t)__cvta_generic_to_shared(smg);
    const int cr = tid >> 2;
    const int cc = tid & 3;

    float acc[2][8][4];
    #pragma unroll
    for (int i = 0; i < 2; i++)
        #pragma unroll
        for (int j = 0; j < 8; j++)
            #pragma unroll
            for (int q = 0; q < 4; q++) acc[i][j][q] = 0.f;

    #define GEMM_ISSUE(ic) do {                                              \
        uint32_t base = sb + ((ic) % 3) * STGW * 4;                          \
        _Pragma("unroll")                                                    \
        for (int i_ = 0; i_ < 2; i_++) {                                     \
            int r_ = cr + i_ * 64;                                           \
            uint32_t doff = (r_ * PADh + cc * 4) * 4;                        \
            cp16(base + doff,                                                \
                 A + (size_t)(m0 + r_) * KW + (ic) * 16 + cc * 4);           \
            cp16(base + 128 * PADh * 4 + doff,                               \
                 B + (size_t)(n0 + r_) * KW + (ic) * 16 + cc * 4);           \
        }                                                                    \
        cp_commit();                                                         \
    } while (0)

    GEMM_ISSUE(0);

    for (int ic = 0; ic < NCHUNK; ic++) {
        if (ic + 1 < NCHUNK) {
            GEMM_ISSUE(ic + 1);
            asm volatile("cp.async.wait_group 1;" ::: "memory");
        } else {
            cp_wait_all();
        }
        __syncthreads();

        const uint32_t* Ab = smg + (ic % 3) * STGW;
        const uint32_t* Bb = Ab + 128 * PADh;
        #pragma unroll
        for (int ks = 0; ks < 2; ks++) {
            int kw = ks * 8 + qd;
            uint32_t af[2][4];
            #pragma unroll
            for (int mt = 0; mt < 2; mt++) {
                int r = wm * 32 + mt * 16 + grp;
                af[mt][0] = Ab[r * PADh + kw];
                af[mt][1] = Ab[(r + 8) * PADh + kw];
                af[mt][2] = Ab[r * PADh + kw + 4];
                af[mt][3] = Ab[(r + 8) * PADh + kw + 4];
            }
            #pragma unroll
            for (int nt = 0; nt < 8; nt++) {
                int c = wn * 64 + nt * 8 + grp;
                uint32_t b0 = Bb[c * PADh + kw];
                uint32_t b1 = Bb[c * PADh + kw + 4];
                mma16816h(acc[0][nt], af[0][0], af[0][1], af[0][2], af[0][3], b0, b1);
                mma16816h(acc[1][nt], af[1][0], af[1][1], af[1][2], af[1][3], b0, b1);
            }
        }
    }

    #pragma unroll
    for (int mt = 0; mt < 2; mt++) {
        #pragma unroll
        for (int nt = 0; nt < 8; nt++) {
            int r = m0 + wm * 32 + mt * 16 + grp;
            int c = n0 + wn * 64 + nt * 8 + qd * 2;
            *(float2*)(C + (size_t)r * N + c) =
                make_float2(acc[mt][nt][0], acc[mt][nt][1]);
            *(float2*)(C + (size_t)(r + 8) * N + c) =
                make_float2(acc[mt][nt][2], acc[mt][nt][3]);
        }
    }
}

// ---------------- block reduction helper (256 threads) ----------------
__device__ __forceinline__ void block_reduce4(float& a, float& b, float& c, float& d) {
    #pragma unroll
    for (int o = 16; o; o >>= 1) {
        a += __shfl_xor_sync(0xffffffffu, a, o);
        b += __shfl_xor_sync(0xffffffffu, b, o);
        c += __shfl_xor_sync(0xffffffffu, c, o);
        d += __shfl_xor_sync(0xffffffffu, d, o);
    }
    __shared__ float s[4][8];
    int w = threadIdx.x >> 5, lane = threadIdx.x & 31;
    if (lane == 0) { s[0][w] = a; s[1][w] = b; s[2][w] = c; s[3][w] = d; }
    __syncthreads();
    a = b = c = d = 0.f;
    #pragma unroll
    for (int i = 0; i < 8; i++) { a += s[0][i]; b += s[1][i]; c += s[2][i]; d += s[3][i]; }
    __syncthreads();
}

// ---------------- kernel 0: RoPE cos/sin table ----------------
__global__ void rope_table_kernel() {
    int idx = blockIdx.x * 256 + threadIdx.x;
    if (idx >= LL * 32) return;
    int l = idx >> 5, fi = idx & 31;
    float invf = powf(10000.0f, -((float)(2 * fi)) / 64.0f);
    float ang  = (float)l * invf;
    g_cs[idx] = make_float2(cosf(ang), sinf(ang));
}

// ---------------- kernel 1: LN1 (fp16 word output) ----------------
__global__ void ln1_kernel(const float* __restrict__ x,
                           const float* __restrict__ w,
                           const float* __restrict__ bia) {
    int t = blockIdx.x;
    int tid = threadIdx.x;
    const float4* xr = (const float4*)(x + (size_t)t * DD);
    float4 v = xr[tid];
    float s  = v.x + v.y + v.z + v.w;
    float ss = v.x*v.x + v.y*v.y + v.z*v.z + v.w*v.w;
    float z0 = 0.f, z1 = 0.f;
    block_reduce4(s, ss, z0, z1);
    float mu  = s * (1.0f / DD);
    float var = ss * (1.0f / DD) - mu * mu;
    float inv = rsqrtf(var + EPS);
    float4 wv = ((const float4*)w)[tid];
    float4 bv = ((const float4*)bia)[tid];
    float4 o;
    o.x = (v.x - mu) * inv * wv.x + bv.x;
    o.y = (v.y - mu) * inv * wv.y + bv.y;
    o.z = (v.z - mu) * inv * wv.z + bv.z;
    o.w = (v.w - mu) * inv * wv.w + bv.w;
    *(uint2*)(g_hh + (size_t)t * KW + tid * 2) =
        make_uint2(h2pack(o.x, o.y), h2pack(o.z, o.w));
}

// ---------------- kernel 3: QK LN + RoPE (table) -> fp16 planes ----------------
__global__ void qk_rope_kernel(const float* __restrict__ qw,
                               const float* __restrict__ kw) {
    int t = blockIdx.x;
    int b = t >> 11;
    int l = t & 2047;
    int tid = threadIdx.x;
    const float4* row = (const float4*)(g_qkv + (size_t)t * 3 * DD);
    float4 q = row[tid];
    float4 k = row[256 + tid];

    float qs  = q.x + q.y + q.z + q.w;
    float qss = q.x*q.x + q.y*q.y + q.z*q.z + q.w*q.w;
    float ks  = k.x + k.y + k.z + k.w;
    float kss = k.x*k.x + k.y*k.y + k.z*k.z + k.w*k.w;
    block_reduce4(qs, qss, ks, kss);
    float muq = qs * (1.0f / DD);
    float vq  = qss * (1.0f / DD) - muq * muq;
    float iq  = rsqrtf(vq + EPS);
    float muk = ks * (1.0f / DD);
    float vk  = kss * (1.0f / DD) - muk * muk;
    float ik  = rsqrtf(vk + EPS);

    __shared__ float qn[DD];
    __shared__ float kn[DD];
    float4 qwv = ((const float4*)qw)[tid];
    float4 kwv = ((const float4*)kw)[tid];
    int d0 = tid * 4;
    qn[d0+0] = (q.x - muq) * iq * qwv.x;
    qn[d0+1] = (q.y - muq) * iq * qwv.y;
    qn[d0+2] = (q.z - muq) * iq * qwv.z;
    qn[d0+3] = (q.w - muq) * iq * qwv.w;
    kn[d0+0] = (k.x - muk) * ik * kwv.x;
    kn[d0+1] = (k.y - muk) * ik * kwv.y;
    kn[d0+2] = (k.z - muk) * ik * kwv.z;
    kn[d0+3] = (k.w - muk) * ik * kwv.w;
    __syncthreads();

    int h   = d0 >> 6;
    int dh0 = d0 & 63;
    float oq[4], ok[4];
    #pragma unroll
    for (int j = 0; j < 4; j++) {
        int dh = dh0 + j;
        int fi = dh & 31;
        float2 cs = g_cs[l * 32 + fi];
        float c = cs.x, s = cs.y;
        float qv = qn[d0 + j];
        float kv = kn[d0 + j];
        float qp = (dh < 32) ? -qn[d0 + j + 32] : qn[d0 + j - 32];
        float kp = (dh < 32) ? -kn[d0 + j + 32] : kn[d0 + j - 32];
        oq[j] = (qv * c + qp * s) * 0.125f;   // fold 1/sqrt(DH) exactly
        ok[j] = kv * c + kp * s;
    }
    size_t pb = ((size_t)(b * HH + h) * LL + l) * 32 + (dh0 >> 1);
    *(uint2*)(g_qf + pb) = make_uint2(h2pack(oq[0], oq[1]), h2pack(oq[2], oq[3]));
    *(uint2*)(g_kf + pb) = make_uint2(h2pack(ok[0], ok[1]), h2pack(ok[2], ok[3]));
}

// ---------------- kernel 3b: V transpose (from g_qkv) -> fp16 plane -------------
__global__ void vtrans_kernel() {
    __shared__ float vs[64 * 65];   // [l][d], pad 65
    const int kt = blockIdx.x, bh = blockIdx.y;
    const int b = bh >> 4, h = bh & 15;
    const int tid = threadIdx.x;
    const float* Vg = g_qkv + ((size_t)(b * LL + kt * 64)) * 3 * DD + 2 * DD + h * 64;
    #pragma unroll
    for (int i = 0; i < 8; i++) {
        int idx = tid + i * 128;
        int l = idx >> 4, c4 = idx & 15;
        float4 v = *(const float4*)(Vg + (size_t)l * 3 * DD + c4 * 4);
        vs[l * 65 + c4 * 4 + 0] = v.x;
        vs[l * 65 + c4 * 4 + 1] = v.y;
        vs[l * 65 + c4 * 4 + 2] = v.z;
        vs[l * 65 + c4 * 4 + 3] = v.w;
    }
    __syncthreads();
    size_t base = ((size_t)bh * 32 + kt) * 64 * 32;
    #pragma unroll
    for (int i = 0; i < 16; i++) {
        int idx = tid + i * 128;
        int d = idx >> 5, lp = idx & 31;
        g_vtf[base + d * 32 + lp] =
            h2pack(vs[(2 * lp) * 65 + d], vs[(2 * lp + 1) * 65 + d]);
    }
}

// ---------------- kernel 4: flash attention, 128-row Q blocks ----
// 256 threads = 8 warps; warp w owns rows 16w..16w+15 of a 128-row Q block.
// K/V staging + barriers amortized over 2x the MMA work; K/V L2 traffic halved.
// Kept kt range is the union for 128 rows (still contiguous; extra tiles are
// exact no-ops) -> bit-identical output. P stays in registers (fragment match).
#define AW 36
#define PL (64 * AW)                  // words per 64-row plane
#define ATTN_SMEM (6 * PL * 4)        // 55296 B: Q(2 planes), K0, V0, K1, V1

__global__ __launch_bounds__(256, 2)
void attn_kernel(const int* __restrict__ seq_id) {
    extern __shared__ uint32_t smw[];
    uint32_t* Qf = smw;                 // [128][AW]
    uint32_t* Kf[2] = { smw + 2 * PL, smw + 4 * PL };
    uint32_t* Vf[2] = { smw + 3 * PL, smw + 5 * PL };
    __shared__ int kseq[2][64];

    const int bh = blockIdx.x, qt = blockIdx.y;   // qt in [0,16): 128-row block
    const int b = bh >> 4, hh = bh & 15;
    const int tid = threadIdx.x;
    const int w = tid >> 5, lane = tid & 31;
    const int grp = lane >> 2, qd = lane & 3;

    const int qbase = b * LL + qt * 128;
    const int qmin = seq_id[qbase];
    const int qmax = seq_id[qbase + 127];

    const uint32_t sb = (uint32_t)__cvta_generic_to_shared(smw);
    const uint32_t sK[2] = { sb + 2 * PL * 4, sb + 4 * PL * 4 };
    const uint32_t sV[2] = { sb + 3 * PL * 4, sb + 5 * PL * 4 };

    // kept range [lo,hi]: contiguous because seq_id is sorted
    int lo = 32, hi = -1;
    for (int kt = 0; kt < 32; kt++) {
        int kmin = seq_id[b * LL + kt * 64];
        int kmax = seq_id[b * LL + kt * 64 + 63];
        if (kmax >= qmin && kmin <= qmax) { if (kt < lo) lo = kt; hi = kt; }
    }

    // stage Q: 128 rows x 32 words (4 cp16 per thread)
    {
        const size_t qrow = ((size_t)bh * LL + qt * 128) * 32;
        #pragma unroll
        for (int i = 0; i < 4; i++) {
            int idx = tid + i * 256;
            int r = idx >> 3, c = idx & 7;
            cp16(sb + (r * AW + c * 4) * 4, g_qf + qrow + r * 32 + c * 4);
        }
        cp_commit();
    }
    // stage K/V + kseq for tile lo into buffer 0 (2 cp16 per array per thread)
    {
        const size_t krow = ((size_t)bh * LL + lo * 64) * 32;
        const size_t vbase = ((size_t)bh * 32 + lo) * 64 * 32;
        #pragma unroll
        for (int i = 0; i < 2; i++) {
            int idx = tid + i * 256;
            int r = idx >> 3, c = idx & 7;
            cp16(sK[0] + (r * AW + c * 4) * 4, g_kf + krow + r * 32 + c * 4);
            cp16(sV[0] + (r * AW + c * 4) * 4, g_vtf + vbase + r * 32 + c * 4);
        }
        cp_commit();
        if (tid < 64) kseq[0][tid] = seq_id[b * LL + lo * 64 + tid];
    }

    const int row0 = w * 16 + grp, row1 = row0 + 8;   // within 128-row block
    const int qs0 = seq_id[qbase + row0];
    const int qs1 = seq_id[qbase + row1];

    float m0 = -1e30f, m1 = -1e30f, l0s = 0.f, l1s = 0.f;
    float O[8][4];
    #pragma unroll
    for (int dt = 0; dt < 8; dt++)
        #pragma unroll
        for (int q = 0; q < 4; q++) O[dt][q] = 0.f;

    for (int kt = lo; kt <= hi; kt++) {
        const int buf = (kt - lo) & 1;
        cp_wait_all();       // current buffer landed
        __syncthreads();     // + all warps done reading buffer being refilled

        if (kt < hi) {
            const int nb = buf ^ 1;
            const size_t krow = ((size_t)bh * LL + (kt + 1) * 64) * 32;
            const size_t vbase = ((size_t)bh * 32 + (kt + 1)) * 64 * 32;
            #pragma unroll
            for (int i = 0; i < 2; i++) {
                int idx = tid + i * 256;
                int r = idx >> 3, c = idx & 7;
                cp16(sK[nb] + (r * AW + c * 4) * 4, g_kf + krow + r * 32 + c * 4);
                cp16(sV[nb] + (r * AW + c * 4) * 4, g_vtf + vbase + r * 32 + c * 4);
            }
            cp_commit();
            if (tid < 64) kseq[nb][tid] = seq_id[b * LL + (kt + 1) * 64 + tid];
        }

        const uint32_t* Kb = Kf[buf];
        const uint32_t* Vb = Vf[buf];

        // ---- S = Q K^T (single fp16 MMA; warp rows row0/row1) ----
        float S[8][4];
        #pragma unroll
        for (int nt = 0; nt < 8; nt++)
            #pragma unroll
            for (int q = 0; q < 4; q++) S[nt][q] = 0.f;
        #pragma unroll
        for (int ks = 0; ks < 4; ks++) {
            int r0w = row0 * AW, r1w = row1 * AW;
            int kw0 = ks * 8 + qd;
            uint32_t a0 = Qf[r0w + kw0],     a1 = Qf[r1w + kw0];
            uint32_t a2 = Qf[r0w + kw0 + 4], a3 = Qf[r1w + kw0 + 4];
            #pragma unroll
            for (int nt = 0; nt < 8; nt++) {
                int nw = (nt * 8 + grp) * AW;
                mma16816h(S[nt], a0, a1, a2, a3, Kb[nw + kw0], Kb[nw + kw0 + 4]);
            }
        }

        // ---- mask ----
        #pragma unroll
        for (int nt = 0; nt < 8; nt++) {
            int c0 = kseq[buf][nt * 8 + 2 * qd];
            int c1 = kseq[buf][nt * 8 + 2 * qd + 1];
            if (c0 != qs0) S[nt][0] = -1e30f;
            if (c1 != qs0) S[nt][1] = -1e30f;
            if (c0 != qs1) S[nt][2] = -1e30f;
            if (c1 != qs1) S[nt][3] = -1e30f;
        }

        // ---- online softmax ----
        float mx0 = -1e30f, mx1 = -1e30f;
        #pragma unroll
        for (int nt = 0; nt < 8; nt++) {
            mx0 = fmaxf(mx0, fmaxf(S[nt][0], S[nt][1]));
            mx1 = fmaxf(mx1, fmaxf(S[nt][2], S[nt][3]));
        }
        mx0 = fmaxf(mx0, __shfl_xor_sync(0xffffffffu, mx0, 1));
        mx0 = fmaxf(mx0, __shfl_xor_sync(0xffffffffu, mx0, 2));
        mx1 = fmaxf(mx1, __shfl_xor_sync(0xffffffffu, mx1, 1));
        mx1 = fmaxf(mx1, __shfl_xor_sync(0xffffffffu, mx1, 2));
        float mn0 = fmaxf(m0, mx0), mn1 = fmaxf(m1, mx1);
        float sc0 = __expf(m0 - mn0), sc1 = __expf(m1 - mn1);
        m0 = mn0; m1 = mn1;
        float s0 = 0.f, s1 = 0.f;
        #pragma unroll
        for (int nt = 0; nt < 8; nt++) {
            S[nt][0] = __expf(S[nt][0] - mn0);
            S[nt][1] = __expf(S[nt][1] - mn0);
            S[nt][2] = __expf(S[nt][2] - mn1);
            S[nt][3] = __expf(S[nt][3] - mn1);
            s0 += S[nt][0] + S[nt][1];
            s1 += S[nt][2] + S[nt][3];
        }
        s0 += __shfl_xor_sync(0xffffffffu, s0, 1);
        s0 += __shfl_xor_sync(0xffffffffu, s0, 2);
        s1 += __shfl_xor_sync(0xffffffffu, s1, 1);
        s1 += __shfl_xor_sync(0xffffffffu, s1, 2);
        l0s = l0s * sc0 + s0;
        l1s = l1s * sc1 + s1;
        #pragma unroll
        for (int dt = 0; dt < 8; dt++) {
            O[dt][0] *= sc0; O[dt][1] *= sc0;
            O[dt][2] *= sc1; O[dt][3] *= sc1;
        }

        // ---- O += P V: P straight from registers (fragment match) ----
        #pragma unroll
        for (int ks = 0; ks < 4; ks++) {
            uint32_t a0 = h2pack(S[2*ks][0],     S[2*ks][1]);
            uint32_t a1 = h2pack(S[2*ks][2],     S[2*ks][3]);
            uint32_t a2 = h2pack(S[2*ks + 1][0], S[2*ks + 1][1]);
            uint32_t a3 = h2pack(S[2*ks + 1][2], S[2*ks + 1][3]);
            int kw0 = ks * 8 + qd;
            #pragma unroll
            for (int dt = 0; dt < 8; dt++) {
                int dw = (dt * 8 + grp) * AW;
                mma16816h(O[dt], a0, a1, a2, a3, Vb[dw + kw0], Vb[dw + kw0 + 4]);
            }
        }
    }

    // epilogue: fp16 ctx words
    float inv0 = 1.0f / l0s, inv1 = 1.0f / l1s;
    const int t0 = qbase + row0;
    const int t1 = qbase + row1;
    #pragma unroll
    for (int dt = 0; dt < 8; dt++) {
        int c = hh * DHH + dt * 8 + 2 * qd;
        g_ctx16[(size_t)t0 * KW + (c >> 1)] =
            h2pack(O[dt][0] * inv0, O[dt][1] * inv0);
        g_ctx16[(size_t)t1 * KW + (c >> 1)] =
            h2pack(O[dt][2] * inv1, O[dt][3] * inv1);
    }
}

// ---------------- launch ----------------
extern "C" void kernel_launch(void* const* d_in, const int* in_sizes, int n_in,
                              void* d_out, int out_size) {
    const float* x     = (const float*)d_in[0];
    const int*   seq   = (const int*)  d_in[1];
    const float* ln1w  = (const float*)d_in[2];
    const float* ln1b  = (const float*)d_in[3];
    const float* wqkv  = (const float*)d_in[4];
    const float* qlnw  = (const float*)d_in[5];
    const float* klnw  = (const float*)d_in[6];
    const float* outw  = (const float*)d_in[7];
    float* out = (float*)d_out;

    void *phh, *pqkv, *pw16, *po16, *pctx16;
    cudaGetSymbolAddress(&phh, g_hh);
    cudaGetSymbolAddress(&pqkv, g_qkv);
    cudaGetSymbolAddress(&pw16, g_wqkv16);
    cudaGetSymbolAddress(&po16, g_outw16);
    cudaGetSymbolAddress(&pctx16, g_ctx16);

    cudaFuncSetAttribute(gemm_mma_fp16, cudaFuncAttributeMaxDynamicSharedMemorySize, GEMM_SMEM);
    cudaFuncSetAttribute(attn_kernel, cudaFuncAttributeMaxDynamicSharedMemorySize, ATTN_SMEM);

    // 0) RoPE table + weight conversions
    rope_table_kernel<<<(LL * 32 + 255) / 256, 256>>>();
    cvt16_kernel<<<(3 * DD * KW + 255) / 256, 256>>>(wqkv, (uint32_t*)pw16, 3 * DD * KW);
    cvt16_kernel<<<(DD * KW + 255) / 256, 256>>>(outw, (uint32_t*)po16, DD * KW);

    // 1) LN1 -> fp16 words
    ln1_kernel<<<TT, 256>>>(x, ln1w, ln1b);

    // 2) QKV GEMM (fp16 operands, cp.async 3-stage)
    gemm_mma_fp16<<<dim3(3 * DD / 128, TT / 128), 256, GEMM_SMEM>>>(
        (const uint32_t*)phh, (const uint32_t*)pw16, (float*)pqkv, 3 * DD);

    // 3) QK LN + RoPE (table) -> fp16 planes
    qk_rope_kernel<<<TT, 256>>>(qlnw, klnw);

    // 3b) V transpose (from g_qkv) -> fp16 plane
    vtrans_kernel<<<dim3(32, NBH), 128>>>();

    // 4) attention (128-row Q blocks, double buffer, P in registers)
    attn_kernel<<<dim3(NBH, LL / 128), 256, ATTN_SMEM>>>(seq);

    // 5) output projection (fp16 operands, cp.async 3-stage)
    gemm_mma_fp16<<<dim3(DD / 128, TT / 128), 256, GEMM_SMEM>>>(
        (const uint32_t*)pctx16, (const uint32_t*)po16, out, DD);
}

// round 16
// speedup vs baseline: 1.0570x; 1.0570x over previous
#include <cuda_runtime.h>
#include <cuda_bf16.h>
#include <cuda_fp16.h>
#include <cstdint>
#include <math.h>

// Problem constants
#define BB 2
#define LL 2048
#define DD 1024
#define HH 16
#define DHH 64
#define TT (BB*LL)          // 4096 tokens
#define EPS 1e-5f
#define NBH (BB*HH)         // 32
#define KW 512              // k-pair words per row (GK/2)

// -------- scratch (device globals: allocation-free rule) --------
__device__ float g_qkv[TT * 3 * DD];      // QKV GEMM output (Q,K region only used)
__device__ float2 g_cs[LL * 32];          // RoPE cos/sin table [l][fi]
// fp16 operand planes for projection GEMMs (half2 k-pair words)
__device__ __align__(16) uint32_t g_hh[TT * KW];        // LN1 out, fp16
__device__ __align__(16) uint32_t g_wqkv16[3 * DD * KW];
__device__ __align__(16) uint32_t g_outw16[DD * KW];
__device__ __align__(16) uint32_t g_ctx16[TT * KW];     // attention out, fp16
// fp16 Q/K planes, word = half2 of adjacent head-dims: [bh][l][32 words]
__device__ __align__(16) uint32_t g_qf[NBH * LL * 32];
__device__ __align__(16) uint32_t g_kf[NBH * LL * 32];
// fp16 transposed V tiles: [bh][kt(32)][d(64)][32 l-pair words]
__device__ __align__(16) uint32_t g_vtf[NBH * 32 * 64 * 32];

__device__ __forceinline__ uint32_t h2pack(float a, float b) {
    __half2 t = __floats2half2_rn(a, b);
    return *reinterpret_cast<uint32_t*>(&t);
}
// fp16 m16n8k16 (all tensor paths)
__device__ __forceinline__ void mma16816h(float* c, uint32_t a0, uint32_t a1,
                                          uint32_t a2, uint32_t a3,
                                          uint32_t b0, uint32_t b1) {
    asm volatile(
        "mma.sync.aligned.m16n8k16.row.col.f32.f16.f16.f32 "
        "{%0,%1,%2,%3}, {%4,%5,%6,%7}, {%8,%9}, {%0,%1,%2,%3};"
        : "+f"(c[0]), "+f"(c[1]), "+f"(c[2]), "+f"(c[3])
        : "r"(a0), "r"(a1), "r"(a2), "r"(a3), "r"(b0), "r"(b1));
}

__device__ __forceinline__ void cp16(uint32_t dst, const void* src) {
    asm volatile("cp.async.ca.shared.global [%0], [%1], 16;"
                 :: "r"(dst), "l"(src));
}
__device__ __forceinline__ void cp_commit() {
    asm volatile("cp.async.commit_group;");
}
__device__ __forceinline__ void cp_wait_all() {
    asm volatile("cp.async.wait_all;" ::: "memory");
}

// ---------------- fused prologue: wqkv cvt + outw cvt + rope table ----------
#define WQKV_WORDS (3 * DD * KW)     // 1572864 = 6144 * 256
#define OUTW_WORDS (DD * KW)         // 524288  = 2048 * 256
#define WQKV_BLKS 6144
#define OUTW_BLKS 2048
#define TBL_BLKS 256                 // 65536 = LL*32
__global__ void prologue_kernel(const float* __restrict__ wqkv,
                                const float* __restrict__ outw) {
    int blk = blockIdx.x;
    if (blk < WQKV_BLKS) {
        int i = blk * 256 + threadIdx.x;
        float2 v = ((const float2*)wqkv)[i];
        g_wqkv16[i] = h2pack(v.x, v.y);
    } else if (blk < WQKV_BLKS + OUTW_BLKS) {
        int i = (blk - WQKV_BLKS) * 256 + threadIdx.x;
        float2 v = ((const float2*)outw)[i];
        g_outw16[i] = h2pack(v.x, v.y);
    } else {
        int idx = (blk - WQKV_BLKS - OUTW_BLKS) * 256 + threadIdx.x;
        int l = idx >> 5, fi = idx & 31;
        float invf = powf(10000.0f, -((float)(2 * fi)) / 64.0f);
        float ang  = (float)l * invf;
        g_cs[idx] = make_float2(cosf(ang), sinf(ang));
    }
}

// ===================== fp16 GEMM, cp.async 3-stage pipeline ==========
// vmode=1 (QKV): CTAs with n0 >= 2048 hold V columns -> store fp16 halves
// directly into g_vtf (transposed layout), skipping the fp32 C write.
// Rounding __float2half_rn(acc) is elementwise identical to the vtrans
// path it replaces -> bit-identical results.
#define NCHUNK 32            // 1024 / 32
#define PADh 20              // 16 k-pair words + 4 pad
#define STGW (2 * 128 * PADh)        // words per stage (A+B)
#define GEMM_SMEM (3 * STGW * 4)     // 61440 B

__device__ __forceinline__ void store_v_half(int t, int d, float v) {
    int b = t >> 11, l = t & 2047;
    int h = d >> 6, dh = d & 63;
    int bh = b * HH + h;
    int kt = l >> 6, lp = (l & 63) >> 1;
    size_t widx = (((size_t)bh * 32 + kt) * 64 + dh) * 32 + lp;
    ((__half*)g_vtf)[widx * 2 + (l & 1)] = __float2half_rn(v);
}

__global__ __launch_bounds__(256)
void gemm_mma_fp16(const uint32_t* __restrict__ A, const uint32_t* __restrict__ B,
                   float* __restrict__ C, int N, int vmode) {
    extern __shared__ uint32_t smg[];

    const int tid = threadIdx.x;
    const int wid = tid >> 5, lane = tid & 31;
    const int grp = lane >> 2, qd = lane & 3;
    const int wm = wid >> 1, wn = wid & 1;
    const int m0 = blockIdx.y * 128;
    const int n0 = blockIdx.x * 128;

    const uint32_t sb = (uint32_t)__cvta_generic_to_shared(smg);
    const int cr = tid >> 2;
    const int cc = tid & 3;

    float acc[2][8][4];
    #pragma unroll
    for (int i = 0; i < 2; i++)
        #pragma unroll
        for (int j = 0; j < 8; j++)
            #pragma unroll
            for (int q = 0; q < 4; q++) acc[i][j][q] = 0.f;

    #define GEMM_ISSUE(ic) do {                                              \
        uint32_t base = sb + ((ic) % 3) * STGW * 4;                          \
        _Pragma("unroll")                                                    \
        for (int i_ = 0; i_ < 2; i_++) {                                     \
            int r_ = cr + i_ * 64;                                           \
            uint32_t doff = (r_ * PADh + cc * 4) * 4;                        \
            cp16(base + doff,                                                \
                 A + (size_t)(m0 + r_) * KW + (ic) * 16 + cc * 4);           \
            cp16(base + 128 * PADh * 4 + doff,                               \
                 B + (size_t)(n0 + r_) * KW + (ic) * 16 + cc * 4);           \
        }                                                                    \
        cp_commit();                                                         \
    } while (0)

    GEMM_ISSUE(0);

    for (int ic = 0; ic < NCHUNK; ic++) {
        if (ic + 1 < NCHUNK) {
            GEMM_ISSUE(ic + 1);
            asm volatile("cp.async.wait_group 1;" ::: "memory");
        } else {
            cp_wait_all();
        }
        __syncthreads();

        const uint32_t* Ab = smg + (ic % 3) * STGW;
        const uint32_t* Bb = Ab + 128 * PADh;
        #pragma unroll
        for (int ks = 0; ks < 2; ks++) {
            int kw = ks * 8 + qd;
            uint32_t af[2][4];
            #pragma unroll
            for (int mt = 0; mt < 2; mt++) {
                int r = wm * 32 + mt * 16 + grp;
                af[mt][0] = Ab[r * PADh + kw];
                af[mt][1] = Ab[(r + 8) * PADh + kw];
                af[mt][2] = Ab[r * PADh + kw + 4];
                af[mt][3] = Ab[(r + 8) * PADh + kw + 4];
            }
            #pragma unroll
            for (int nt = 0; nt < 8; nt++) {
                int c = wn * 64 + nt * 8 + grp;
                uint32_t b0 = Bb[c * PADh + kw];
                uint32_t b1 = Bb[c * PADh + kw + 4];
                mma16816h(acc[0][nt], af[0][0], af[0][1], af[0][2], af[0][3], b0, b1);
                mma16816h(acc[1][nt], af[1][0], af[1][1], af[1][2], af[1][3], b0, b1);
            }
        }
    }

    if (vmode && n0 >= 2 * DD) {
        // V region: transposed fp16 stores into g_vtf (replaces vtrans)
        #pragma unroll
        for (int mt = 0; mt < 2; mt++) {
            #pragma unroll
            for (int nt = 0; nt < 8; nt++) {
                int r = m0 + wm * 32 + mt * 16 + grp;
                int d0v = (n0 - 2 * DD) + wn * 64 + nt * 8 + qd * 2;
                store_v_half(r,     d0v,     acc[mt][nt][0]);
                store_v_half(r,     d0v + 1, acc[mt][nt][1]);
                store_v_half(r + 8, d0v,     acc[mt][nt][2]);
                store_v_half(r + 8, d0v + 1, acc[mt][nt][3]);
            }
        }
    } else {
        #pragma unroll
        for (int mt = 0; mt < 2; mt++) {
            #pragma unroll
            for (int nt = 0; nt < 8; nt++) {
                int r = m0 + wm * 32 + mt * 16 + grp;
                int c = n0 + wn * 64 + nt * 8 + qd * 2;
                *(float2*)(C + (size_t)r * N + c) =
                    make_float2(acc[mt][nt][0], acc[mt][nt][1]);
                *(float2*)(C + (size_t)(r + 8) * N + c) =
                    make_float2(acc[mt][nt][2], acc[mt][nt][3]);
            }
        }
    }
}

// ---------------- block reduction helper (256 threads) ----------------
__device__ __forceinline__ void block_reduce4(float& a, float& b, float& c, float& d) {
    #pragma unroll
    for (int o = 16; o; o >>= 1) {
        a += __shfl_xor_sync(0xffffffffu, a, o);
        b += __shfl_xor_sync(0xffffffffu, b, o);
        c += __shfl_xor_sync(0xffffffffu, c, o);
        d += __shfl_xor_sync(0xffffffffu, d, o);
    }
    __shared__ float s[4][8];
    int w = threadIdx.x >> 5, lane = threadIdx.x & 31;
    if (lane == 0) { s[0][w] = a; s[1][w] = b; s[2][w] = c; s[3][w] = d; }
    __syncthreads();
    a = b = c = d = 0.f;
    #pragma unroll
    for (int i = 0; i < 8; i++) { a += s[0][i]; b += s[1][i]; c += s[2][i]; d += s[3][i]; }
    __syncthreads();
}

// ---------------- kernel 1: LN1 (fp16 word output) ----------------
__global__ void ln1_kernel(const float* __restrict__ x,
                           const float* __restrict__ w,
                           const float* __restrict__ bia) {
    int t = blockIdx.x;
    int tid = threadIdx.x;
    const float4* xr = (const float4*)(x + (size_t)t * DD);
    float4 v = xr[tid];
    float s  = v.x + v.y + v.z + v.w;
    float ss = v.x*v.x + v.y*v.y + v.z*v.z + v.w*v.w;
    float z0 = 0.f, z1 = 0.f;
    block_reduce4(s, ss, z0, z1);
    float mu  = s * (1.0f / DD);
    float var = ss * (1.0f / DD) - mu * mu;
    float inv = rsqrtf(var + EPS);
    float4 wv = ((const float4*)w)[tid];
    float4 bv = ((const float4*)bia)[tid];
    float4 o;
    o.x = (v.x - mu) * inv * wv.x + bv.x;
    o.y = (v.y - mu) * inv * wv.y + bv.y;
    o.z = (v.z - mu) * inv * wv.z + bv.z;
    o.w = (v.w - mu) * inv * wv.w + bv.w;
    *(uint2*)(g_hh + (size_t)t * KW + tid * 2) =
        make_uint2(h2pack(o.x, o.y), h2pack(o.z, o.w));
}

// ---------------- kernel 3: QK LN + RoPE (table) -> fp16 planes ----------------
__global__ void qk_rope_kernel(const float* __restrict__ qw,
                               const float* __restrict__ kw) {
    int t = blockIdx.x;
    int b = t >> 11;
    int l = t & 2047;
    int tid = threadIdx.x;
    const float4* row = (const float4*)(g_qkv + (size_t)t * 3 * DD);
    float4 q = row[tid];
    float4 k = row[256 + tid];

    float qs  = q.x + q.y + q.z + q.w;
    float qss = q.x*q.x + q.y*q.y + q.z*q.z + q.w*q.w;
    float ks  = k.x + k.y + k.z + k.w;
    float kss = k.x*k.x + k.y*k.y + k.z*k.z + k.w*k.w;
    block_reduce4(qs, qss, ks, kss);
    float muq = qs * (1.0f / DD);
    float vq  = qss * (1.0f / DD) - muq * muq;
    float iq  = rsqrtf(vq + EPS);
    float muk = ks * (1.0f / DD);
    float vk  = kss * (1.0f / DD) - muk * muk;
    float ik  = rsqrtf(vk + EPS);

    __shared__ float qn[DD];
    __shared__ float kn[DD];
    float4 qwv = ((const float4*)qw)[tid];
    float4 kwv = ((const float4*)kw)[tid];
    int d0 = tid * 4;
    qn[d0+0] = (q.x - muq) * iq * qwv.x;
    qn[d0+1] = (q.y - muq) * iq * qwv.y;
    qn[d0+2] = (q.z - muq) * iq * qwv.z;
    qn[d0+3] = (q.w - muq) * iq * qwv.w;
    kn[d0+0] = (k.x - muk) * ik * kwv.x;
    kn[d0+1] = (k.y - muk) * ik * kwv.y;
    kn[d0+2] = (k.z - muk) * ik * kwv.z;
    kn[d0+3] = (k.w - muk) * ik * kwv.w;
    __syncthreads();

    int h   = d0 >> 6;
    int dh0 = d0 & 63;
    float oq[4], ok[4];
    #pragma unroll
    for (int j = 0; j < 4; j++) {
        int dh = dh0 + j;
        int fi = dh & 31;
        float2 cs = g_cs[l * 32 + fi];
        float c = cs.x, s = cs.y;
        float qv = qn[d0 + j];
        float kv = kn[d0 + j];
        float qp = (dh < 32) ? -qn[d0 + j + 32] : qn[d0 + j - 32];
        float kp = (dh < 32) ? -kn[d0 + j + 32] : kn[d0 + j - 32];
        oq[j] = (qv * c + qp * s) * 0.125f;   // fold 1/sqrt(DH) exactly
        ok[j] = kv * c + kp * s;
    }
    size_t pb = ((size_t)(b * HH + h) * LL + l) * 32 + (dh0 >> 1);
    *(uint2*)(g_qf + pb) = make_uint2(h2pack(oq[0], oq[1]), h2pack(oq[2], oq[3]));
    *(uint2*)(g_kf + pb) = make_uint2(h2pack(ok[0], ok[1]), h2pack(ok[2], ok[3]));
}

// ---------------- kernel 4: flash attention (R14: 64-row Q, double buffer,
// P in registers, one __syncthreads per tile) ----
#define AW 36
#define PL (64 * AW)                  // words per plane
#define ATTN_SMEM (5 * PL * 4)        // 46080 B: Q, K0, V0, K1, V1

__global__ __launch_bounds__(128, 4)
void attn_kernel(const int* __restrict__ seq_id) {
    extern __shared__ uint32_t smw[];
    uint32_t* Qf = smw;                 // [64][AW]
    uint32_t* Kf[2] = { smw + 1 * PL, smw + 3 * PL };
    uint32_t* Vf[2] = { smw + 2 * PL, smw + 4 * PL };
    __shared__ int kseq[2][64];

    const int bh = blockIdx.x, qt = blockIdx.y;
    const int b = bh >> 4, hh = bh & 15;
    const int tid = threadIdx.x;
    const int w = tid >> 5, lane = tid & 31;
    const int grp = lane >> 2, qd = lane & 3;

    const int qbase = b * LL + qt * 64;
    const int qmin = seq_id[qbase];
    const int qmax = seq_id[qbase + 63];

    const uint32_t sb = (uint32_t)__cvta_generic_to_shared(smw);
    const uint32_t sK[2] = { sb + 1 * PL * 4, sb + 3 * PL * 4 };
    const uint32_t sV[2] = { sb + 2 * PL * 4, sb + 4 * PL * 4 };

    // kept range [lo,hi]: contiguous because seq_id is sorted
    int lo = 32, hi = -1;
    for (int kt = 0; kt < 32; kt++) {
        int kmin = seq_id[b * LL + kt * 64];
        int kmax = seq_id[b * LL + kt * 64 + 63];
        if (kmax >= qmin && kmin <= qmax) { if (kt < lo) lo = kt; hi = kt; }
    }

    // stage Q
    {
        const size_t qrow = ((size_t)bh * LL + qt * 64) * 32;
        #pragma unroll
        for (int i = 0; i < 4; i++) {
            int idx = tid + i * 128;
            int r = idx >> 3, c = idx & 7;
            cp16(sb + (r * AW + c * 4) * 4, g_qf + qrow + r * 32 + c * 4);
        }
        cp_commit();
    }
    // stage K/V + kseq for tile lo into buffer 0
    {
        const size_t krow = ((size_t)bh * LL + lo * 64) * 32;
        const size_t vbase = ((size_t)bh * 32 + lo) * 64 * 32;
        #pragma unroll
        for (int i = 0; i < 4; i++) {
            int idx = tid + i * 128;
            int r = idx >> 3, c = idx & 7;
            cp16(sK[0] + (r * AW + c * 4) * 4, g_kf + krow + r * 32 + c * 4);
            cp16(sV[0] + (r * AW + c * 4) * 4, g_vtf + vbase + r * 32 + c * 4);
        }
        cp_commit();
        if (tid < 64) kseq[0][tid] = seq_id[b * LL + lo * 64 + tid];
    }

    const int row0 = w * 16 + grp, row1 = row0 + 8;
    const int qs0 = seq_id[qbase + row0];
    const int qs1 = seq_id[qbase + row1];

    float m0 = -1e30f, m1 = -1e30f, l0s = 0.f, l1s = 0.f;
    float O[8][4];
    #pragma unroll
    for (int dt = 0; dt < 8; dt++)
        #pragma unroll
        for (int q = 0; q < 4; q++) O[dt][q] = 0.f;

    for (int kt = lo; kt <= hi; kt++) {
        const int buf = (kt - lo) & 1;
        cp_wait_all();
        __syncthreads();

        if (kt < hi) {
            const int nb = buf ^ 1;
            const size_t krow = ((size_t)bh * LL + (kt + 1) * 64) * 32;
            const size_t vbase = ((size_t)bh * 32 + (kt + 1)) * 64 * 32;
            #pragma unroll
            for (int i = 0; i < 4; i++) {
                int idx = tid + i * 128;
                int r = idx >> 3, c = idx & 7;
                cp16(sK[nb] + (r * AW + c * 4) * 4, g_kf + krow + r * 32 + c * 4);
                cp16(sV[nb] + (r * AW + c * 4) * 4, g_vtf + vbase + r * 32 + c * 4);
            }
            cp_commit();
            if (tid < 64) kseq[nb][tid] = seq_id[b * LL + (kt + 1) * 64 + tid];
        }

        const uint32_t* Kb = Kf[buf];
        const uint32_t* Vb = Vf[buf];

        // ---- S = Q K^T ----
        float S[8][4];
        #pragma unroll
        for (int nt = 0; nt < 8; nt++)
            #pragma unroll
            for (int q = 0; q < 4; q++) S[nt][q] = 0.f;
        #pragma unroll
        for (int ks = 0; ks < 4; ks++) {
            int r0w = (w * 16 + grp) * AW, r1w = (w * 16 + grp + 8) * AW;
            int kw0 = ks * 8 + qd;
            uint32_t a0 = Qf[r0w + kw0],     a1 = Qf[r1w + kw0];
            uint32_t a2 = Qf[r0w + kw0 + 4], a3 = Qf[r1w + kw0 + 4];
            #pragma unroll
            for (int nt = 0; nt < 8; nt++) {
                int nw = (nt * 8 + grp) * AW;
                mma16816h(S[nt], a0, a1, a2, a3, Kb[nw + kw0], Kb[nw + kw0 + 4]);
            }
        }

        // ---- mask ----
        #pragma unroll
        for (int nt = 0; nt < 8; nt++) {
            int c0 = kseq[buf][nt * 8 + 2 * qd];
            int c1 = kseq[buf][nt * 8 + 2 * qd + 1];
            if (c0 != qs0) S[nt][0] = -1e30f;
            if (c1 != qs0) S[nt][1] = -1e30f;
            if (c0 != qs1) S[nt][2] = -1e30f;
            if (c1 != qs1) S[nt][3] = -1e30f;
        }

        // ---- online softmax ----
        float mx0 = -1e30f, mx1 = -1e30f;
        #pragma unroll
        for (int nt = 0; nt < 8; nt++) {
            mx0 = fmaxf(mx0, fmaxf(S[nt][0], S[nt][1]));
            mx1 = fmaxf(mx1, fmaxf(S[nt][2], S[nt][3]));
        }
        mx0 = fmaxf(mx0, __shfl_xor_sync(0xffffffffu, mx0, 1));
        mx0 = fmaxf(mx0, __shfl_xor_sync(0xffffffffu, mx0, 2));
        mx1 = fmaxf(mx1, __shfl_xor_sync(0xffffffffu, mx1, 1));
        mx1 = fmaxf(mx1, __shfl_xor_sync(0xffffffffu, mx1, 2));
        float mn0 = fmaxf(m0, mx0), mn1 = fmaxf(m1, mx1);
        float sc0 = __expf(m0 - mn0), sc1 = __expf(m1 - mn1);
        m0 = mn0; m1 = mn1;
        float s0 = 0.f, s1 = 0.f;
        #pragma unroll
        for (int nt = 0; nt < 8; nt++) {
            S[nt][0] = __expf(S[nt][0] - mn0);
            S[nt][1] = __expf(S[nt][1] - mn0);
            S[nt][2] = __expf(S[nt][2] - mn1);
            S[nt][3] = __expf(S[nt][3] - mn1);
            s0 += S[nt][0] + S[nt][1];
            s1 += S[nt][2] + S[nt][3];
        }
        s0 += __shfl_xor_sync(0xffffffffu, s0, 1);
        s0 += __shfl_xor_sync(0xffffffffu, s0, 2);
        s1 += __shfl_xor_sync(0xffffffffu, s1, 1);
        s1 += __shfl_xor_sync(0xffffffffu, s1, 2);
        l0s = l0s * sc0 + s0;
        l1s = l1s * sc1 + s1;
        #pragma unroll
        for (int dt = 0; dt < 8; dt++) {
            O[dt][0] *= sc0; O[dt][1] *= sc0;
            O[dt][2] *= sc1; O[dt][3] *= sc1;
        }

        // ---- O += P V: P straight from registers (fragment match) ----
        #pragma unroll
        for (int ks = 0; ks < 4; ks++) {
            uint32_t a0 = h2pack(S[2*ks][0],     S[2*ks][1]);
            uint32_t a1 = h2pack(S[2*ks][2],     S[2*ks][3]);
            uint32_t a2 = h2pack(S[2*ks + 1][0], S[2*ks + 1][1]);
            uint32_t a3 = h2pack(S[2*ks + 1][2], S[2*ks + 1][3]);
            int kw0 = ks * 8 + qd;
            #pragma unroll
            for (int dt = 0; dt < 8; dt++) {
                int dw = (dt * 8 + grp) * AW;
                mma16816h(O[dt], a0, a1, a2, a3, Vb[dw + kw0], Vb[dw + kw0 + 4]);
            }
        }
    }

    // epilogue: fp16 ctx words
    float inv0 = 1.0f / l0s, inv1 = 1.0f / l1s;
    const int t0 = b * LL + qt * 64 + row0;
    const int t1 = b * LL + qt * 64 + row1;
    #pragma unroll
    for (int dt = 0; dt < 8; dt++) {
        int c = hh * DHH + dt * 8 + 2 * qd;
        g_ctx16[(size_t)t0 * KW + (c >> 1)] =
            h2pack(O[dt][0] * inv0, O[dt][1] * inv0);
        g_ctx16[(size_t)t1 * KW + (c >> 1)] =
            h2pack(O[dt][2] * inv1, O[dt][3] * inv1);
    }
}

// ---------------- launch ----------------
extern "C" void kernel_launch(void* const* d_in, const int* in_sizes, int n_in,
                              void* d_out, int out_size) {
    const float* x     = (const float*)d_in[0];
    const int*   seq   = (const int*)  d_in[1];
    const float* ln1w  = (const float*)d_in[2];
    const float* ln1b  = (const float*)d_in[3];
    const float* wqkv  = (const float*)d_in[4];
    const float* qlnw  = (const float*)d_in[5];
    const float* klnw  = (const float*)d_in[6];
    const float* outw  = (const float*)d_in[7];
    float* out = (float*)d_out;

    void *phh, *pqkv, *pw16, *po16, *pctx16;
    cudaGetSymbolAddress(&phh, g_hh);
    cudaGetSymbolAddress(&pqkv, g_qkv);
    cudaGetSymbolAddress(&pw16, g_wqkv16);
    cudaGetSymbolAddress(&po16, g_outw16);
    cudaGetSymbolAddress(&pctx16, g_ctx16);

    cudaFuncSetAttribute(gemm_mma_fp16, cudaFuncAttributeMaxDynamicSharedMemorySize, GEMM_SMEM);
    cudaFuncSetAttribute(attn_kernel, cudaFuncAttributeMaxDynamicSharedMemorySize, ATTN_SMEM);

    // 0) fused prologue: weight conversions + RoPE table
    prologue_kernel<<<WQKV_BLKS + OUTW_BLKS + TBL_BLKS, 256>>>(wqkv, outw);

    // 1) LN1 -> fp16 words
    ln1_kernel<<<TT, 256>>>(x, ln1w, ln1b);

    // 2) QKV GEMM; V columns stored transposed fp16 straight into g_vtf
    gemm_mma_fp16<<<dim3(3 * DD / 128, TT / 128), 256, GEMM_SMEM>>>(
        (const uint32_t*)phh, (const uint32_t*)pw16, (float*)pqkv, 3 * DD, 1);

    // 3) QK LN + RoPE (table) -> fp16 planes
    qk_rope_kernel<<<TT, 256>>>(qlnw, klnw);

    // 4) attention (R14 structure: double buffer + P in registers)
    attn_kernel<<<dim3(NBH, LL / 64), 128, ATTN_SMEM>>>(seq);

    // 5) output projection
    gemm_mma_fp16<<<dim3(DD / 128, TT / 128), 256, GEMM_SMEM>>>(
        (const uint32_t*)pctx16, (const uint32_t*)po16, out, DD, 0);
}

// round 17
// speedup vs baseline: 1.0667x; 1.0091x over previous
#include <cuda_runtime.h>
#include <cuda_bf16.h>
#include <cuda_fp16.h>
#include <cstdint>
#include <math.h>

// Problem constants
#define BB 2
#define LL 2048
#define DD 1024
#define HH 16
#define DHH 64
#define TT (BB*LL)          // 4096 tokens
#define EPS 1e-5f
#define NBH (BB*HH)         // 32
#define KW 512              // k-pair words per row (GK/2)

// -------- scratch (device globals: allocation-free rule) --------
__device__ float2 g_cs[LL * 32];          // RoPE cos/sin table [l][fi]
// fp16 Q/K from QKV GEMM: [t][1024 words] (cols 0..511 = Q, 512..1023 = K)
__device__ __align__(16) uint32_t g_qk16[TT * 1024];
// fp16 operand planes for projection GEMMs (half2 k-pair words)
__device__ __align__(16) uint32_t g_hh[TT * KW];        // LN1 out, fp16
__device__ __align__(16) uint32_t g_wqkv16[3 * DD * KW];
__device__ __align__(16) uint32_t g_outw16[DD * KW];
__device__ __align__(16) uint32_t g_ctx16[TT * KW];     // attention out, fp16
// fp16 Q/K planes, word = half2 of adjacent head-dims: [bh][l][32 words]
__device__ __align__(16) uint32_t g_qf[NBH * LL * 32];
__device__ __align__(16) uint32_t g_kf[NBH * LL * 32];
// fp16 transposed V tiles: [bh][kt(32)][d(64)][32 l-pair words]
__device__ __align__(16) uint32_t g_vtf[NBH * 32 * 64 * 32];

__device__ __forceinline__ uint32_t h2pack(float a, float b) {
    __half2 t = __floats2half2_rn(a, b);
    return *reinterpret_cast<uint32_t*>(&t);
}
// fp16 m16n8k16 (all tensor paths)
__device__ __forceinline__ void mma16816h(float* c, uint32_t a0, uint32_t a1,
                                          uint32_t a2, uint32_t a3,
                                          uint32_t b0, uint32_t b1) {
    asm volatile(
        "mma.sync.aligned.m16n8k16.row.col.f32.f16.f16.f32 "
        "{%0,%1,%2,%3}, {%4,%5,%6,%7}, {%8,%9}, {%0,%1,%2,%3};"
        : "+f"(c[0]), "+f"(c[1]), "+f"(c[2]), "+f"(c[3])
        : "r"(a0), "r"(a1), "r"(a2), "r"(a3), "r"(b0), "r"(b1));
}

__device__ __forceinline__ void cp16(uint32_t dst, const void* src) {
    asm volatile("cp.async.ca.shared.global [%0], [%1], 16;"
                 :: "r"(dst), "l"(src));
}
__device__ __forceinline__ void cp_commit() {
    asm volatile("cp.async.commit_group;");
}
__device__ __forceinline__ void cp_wait_all() {
    asm volatile("cp.async.wait_all;" ::: "memory");
}

// ---------------- fused prologue: wqkv cvt + outw cvt + rope table ----------
#define WQKV_BLKS 6144
#define OUTW_BLKS 2048
#define TBL_BLKS 256                 // 65536 = LL*32
__global__ void prologue_kernel(const float* __restrict__ wqkv,
                                const float* __restrict__ outw) {
    int blk = blockIdx.x;
    if (blk < WQKV_BLKS) {
        int i = blk * 256 + threadIdx.x;
        float2 v = ((const float2*)wqkv)[i];
        g_wqkv16[i] = h2pack(v.x, v.y);
    } else if (blk < WQKV_BLKS + OUTW_BLKS) {
        int i = (blk - WQKV_BLKS) * 256 + threadIdx.x;
        float2 v = ((const float2*)outw)[i];
        g_outw16[i] = h2pack(v.x, v.y);
    } else {
        int idx = (blk - WQKV_BLKS - OUTW_BLKS) * 256 + threadIdx.x;
        int l = idx >> 5, fi = idx & 31;
        float invf = powf(10000.0f, -((float)(2 * fi)) / 64.0f);
        float ang  = (float)l * invf;
        g_cs[idx] = make_float2(cosf(ang), sinf(ang));
    }
}

// ===================== fp16 GEMM, cp.async 3-stage pipeline ==========
// vmode=1 (QKV): n0 >= 2048 -> V columns stored transposed fp16 into g_vtf;
// n0 < 2048 -> Q/K columns stored as packed fp16 words into g_qk16.
#define NCHUNK 32            // 1024 / 32
#define PADh 20              // 16 k-pair words + 4 pad
#define STGW (2 * 128 * PADh)        // words per stage (A+B)
#define GEMM_SMEM (3 * STGW * 4)     // 61440 B

__device__ __forceinline__ void store_v_half(int t, int d, float v) {
    int b = t >> 11, l = t & 2047;
    int h = d >> 6, dh = d & 63;
    int bh = b * HH + h;
    int kt = l >> 6, lp = (l & 63) >> 1;
    size_t widx = (((size_t)bh * 32 + kt) * 64 + dh) * 32 + lp;
    ((__half*)g_vtf)[widx * 2 + (l & 1)] = __float2half_rn(v);
}

__global__ __launch_bounds__(256)
void gemm_mma_fp16(const uint32_t* __restrict__ A, const uint32_t* __restrict__ B,
                   float* __restrict__ C, int N, int vmode) {
    extern __shared__ uint32_t smg[];

    const int tid = threadIdx.x;
    const int wid = tid >> 5, lane = tid & 31;
    const int grp = lane >> 2, qd = lane & 3;
    const int wm = wid >> 1, wn = wid & 1;
    const int m0 = blockIdx.y * 128;
    const int n0 = blockIdx.x * 128;

    const uint32_t sb = (uint32_t)__cvta_generic_to_shared(smg);
    const int cr = tid >> 2;
    const int cc = tid & 3;

    float acc[2][8][4];
    #pragma unroll
    for (int i = 0; i < 2; i++)
        #pragma unroll
        for (int j = 0; j < 8; j++)
            #pragma unroll
            for (int q = 0; q < 4; q++) acc[i][j][q] = 0.f;

    #define GEMM_ISSUE(ic) do {                                              \
        uint32_t base = sb + ((ic) % 3) * STGW * 4;                          \
        _Pragma("unroll")                                                    \
        for (int i_ = 0; i_ < 2; i_++) {                                     \
            int r_ = cr + i_ * 64;                                           \
            uint32_t doff = (r_ * PADh + cc * 4) * 4;                        \
            cp16(base + doff,                                                \
                 A + (size_t)(m0 + r_) * KW + (ic) * 16 + cc * 4);           \
            cp16(base + 128 * PADh * 4 + doff,                               \
                 B + (size_t)(n0 + r_) * KW + (ic) * 16 + cc * 4);           \
        }                                                                    \
        cp_commit();                                                         \
    } while (0)

    GEMM_ISSUE(0);

    for (int ic = 0; ic < NCHUNK; ic++) {
        if (ic + 1 < NCHUNK) {
            GEMM_ISSUE(ic + 1);
            asm volatile("cp.async.wait_group 1;" ::: "memory");
        } else {
            cp_wait_all();
        }
        __syncthreads();

        const uint32_t* Ab = smg + (ic % 3) * STGW;
        const uint32_t* Bb = Ab + 128 * PADh;
        #pragma unroll
        for (int ks = 0; ks < 2; ks++) {
            int kw = ks * 8 + qd;
            uint32_t af[2][4];
            #pragma unroll
            for (int mt = 0; mt < 2; mt++) {
                int r = wm * 32 + mt * 16 + grp;
                af[mt][0] = Ab[r * PADh + kw];
                af[mt][1] = Ab[(r + 8) * PADh + kw];
                af[mt][2] = Ab[r * PADh + kw + 4];
                af[mt][3] = Ab[(r + 8) * PADh + kw + 4];
            }
            #pragma unroll
            for (int nt = 0; nt < 8; nt++) {
                int c = wn * 64 + nt * 8 + grp;
                uint32_t b0 = Bb[c * PADh + kw];
                uint32_t b1 = Bb[c * PADh + kw + 4];
                mma16816h(acc[0][nt], af[0][0], af[0][1], af[0][2], af[0][3], b0, b1);
                mma16816h(acc[1][nt], af[1][0], af[1][1], af[1][2], af[1][3], b0, b1);
            }
        }
    }

    if (vmode) {
        if (n0 >= 2 * DD) {
            // V region: transposed fp16 stores into g_vtf
            #pragma unroll
            for (int mt = 0; mt < 2; mt++) {
                #pragma unroll
                for (int nt = 0; nt < 8; nt++) {
                    int r = m0 + wm * 32 + mt * 16 + grp;
                    int d0v = (n0 - 2 * DD) + wn * 64 + nt * 8 + qd * 2;
                    store_v_half(r,     d0v,     acc[mt][nt][0]);
                    store_v_half(r,     d0v + 1, acc[mt][nt][1]);
                    store_v_half(r + 8, d0v,     acc[mt][nt][2]);
                    store_v_half(r + 8, d0v + 1, acc[mt][nt][3]);
                }
            }
        } else {
            // Q/K region: packed fp16 word stores into g_qk16
            #pragma unroll
            for (int mt = 0; mt < 2; mt++) {
                #pragma unroll
                for (int nt = 0; nt < 8; nt++) {
                    int r = m0 + wm * 32 + mt * 16 + grp;
                    int c = n0 + wn * 64 + nt * 8 + qd * 2;   // even
                    g_qk16[(size_t)r * 1024 + (c >> 1)] =
                        h2pack(acc[mt][nt][0], acc[mt][nt][1]);
                    g_qk16[(size_t)(r + 8) * 1024 + (c >> 1)] =
                        h2pack(acc[mt][nt][2], acc[mt][nt][3]);
                }
            }
        }
    } else {
        #pragma unroll
        for (int mt = 0; mt < 2; mt++) {
            #pragma unroll
            for (int nt = 0; nt < 8; nt++) {
                int r = m0 + wm * 32 + mt * 16 + grp;
                int c = n0 + wn * 64 + nt * 8 + qd * 2;
                *(float2*)(C + (size_t)r * N + c) =
                    make_float2(acc[mt][nt][0], acc[mt][nt][1]);
                *(float2*)(C + (size_t)(r + 8) * N + c) =
                    make_float2(acc[mt][nt][2], acc[mt][nt][3]);
            }
        }
    }
}

// ---------------- block reduction helper (256 threads) ----------------
__device__ __forceinline__ void block_reduce4(float& a, float& b, float& c, float& d) {
    #pragma unroll
    for (int o = 16; o; o >>= 1) {
        a += __shfl_xor_sync(0xffffffffu, a, o);
        b += __shfl_xor_sync(0xffffffffu, b, o);
        c += __shfl_xor_sync(0xffffffffu, c, o);
        d += __shfl_xor_sync(0xffffffffu, d, o);
    }
    __shared__ float s[4][8];
    int w = threadIdx.x >> 5, lane = threadIdx.x & 31;
    if (lane == 0) { s[0][w] = a; s[1][w] = b; s[2][w] = c; s[3][w] = d; }
    __syncthreads();
    a = b = c = d = 0.f;
    #pragma unroll
    for (int i = 0; i < 8; i++) { a += s[0][i]; b += s[1][i]; c += s[2][i]; d += s[3][i]; }
    __syncthreads();
}

// ---------------- kernel 1: LN1 (fp16 word output) ----------------
__global__ void ln1_kernel(const float* __restrict__ x,
                           const float* __restrict__ w,
                           const float* __restrict__ bia) {
    int t = blockIdx.x;
    int tid = threadIdx.x;
    const float4* xr = (const float4*)(x + (size_t)t * DD);
    float4 v = xr[tid];
    float s  = v.x + v.y + v.z + v.w;
    float ss = v.x*v.x + v.y*v.y + v.z*v.z + v.w*v.w;
    float z0 = 0.f, z1 = 0.f;
    block_reduce4(s, ss, z0, z1);
    float mu  = s * (1.0f / DD);
    float var = ss * (1.0f / DD) - mu * mu;
    float inv = rsqrtf(var + EPS);
    float4 wv = ((const float4*)w)[tid];
    float4 bv = ((const float4*)bia)[tid];
    float4 o;
    o.x = (v.x - mu) * inv * wv.x + bv.x;
    o.y = (v.y - mu) * inv * wv.y + bv.y;
    o.z = (v.z - mu) * inv * wv.z + bv.z;
    o.w = (v.w - mu) * inv * wv.w + bv.w;
    *(uint2*)(g_hh + (size_t)t * KW + tid * 2) =
        make_uint2(h2pack(o.x, o.y), h2pack(o.z, o.w));
}

// ---------------- kernel 3: QK LN + RoPE (table) -> fp16 planes ----------------
// reads fp16 Q/K from g_qk16 (stats in fp32 over fp16-rounded values)
__global__ void qk_rope_kernel(const float* __restrict__ qw,
                               const float* __restrict__ kw) {
    int t = blockIdx.x;
    int b = t >> 11;
    int l = t & 2047;
    int tid = threadIdx.x;
    const uint32_t* row = g_qk16 + (size_t)t * 1024;
    uint2 qw2 = *(const uint2*)(row + tid * 2);
    uint2 kw2 = *(const uint2*)(row + 512 + tid * 2);
    float2 qa = __half22float2(*reinterpret_cast<__half2*>(&qw2.x));
    float2 qb = __half22float2(*reinterpret_cast<__half2*>(&qw2.y));
    float2 ka = __half22float2(*reinterpret_cast<__half2*>(&kw2.x));
    float2 kb = __half22float2(*reinterpret_cast<__half2*>(&kw2.y));
    float4 q = make_float4(qa.x, qa.y, qb.x, qb.y);
    float4 k = make_float4(ka.x, ka.y, kb.x, kb.y);

    float qs  = q.x + q.y + q.z + q.w;
    float qss = q.x*q.x + q.y*q.y + q.z*q.z + q.w*q.w;
    float ks  = k.x + k.y + k.z + k.w;
    float kss = k.x*k.x + k.y*k.y + k.z*k.z + k.w*k.w;
    block_reduce4(qs, qss, ks, kss);
    float muq = qs * (1.0f / DD);
    float vq  = qss * (1.0f / DD) - muq * muq;
    float iq  = rsqrtf(vq + EPS);
    float muk = ks * (1.0f / DD);
    float vk  = kss * (1.0f / DD) - muk * muk;
    float ik  = rsqrtf(vk + EPS);

    __shared__ float qn[DD];
    __shared__ float kn[DD];
    float4 qwv = ((const float4*)qw)[tid];
    float4 kwv = ((const float4*)kw)[tid];
    int d0 = tid * 4;
    qn[d0+0] = (q.x - muq) * iq * qwv.x;
    qn[d0+1] = (q.y - muq) * iq * qwv.y;
    qn[d0+2] = (q.z - muq) * iq * qwv.z;
    qn[d0+3] = (q.w - muq) * iq * qwv.w;
    kn[d0+0] = (k.x - muk) * ik * kwv.x;
    kn[d0+1] = (k.y - muk) * ik * kwv.y;
    kn[d0+2] = (k.z - muk) * ik * kwv.z;
    kn[d0+3] = (k.w - muk) * ik * kwv.w;
    __syncthreads();

    int h   = d0 >> 6;
    int dh0 = d0 & 63;
    float oq[4], ok[4];
    #pragma unroll
    for (int j = 0; j < 4; j++) {
        int dh = dh0 + j;
        int fi = dh & 31;
        float2 cs = g_cs[l * 32 + fi];
        float c = cs.x, s = cs.y;
        float qv = qn[d0 + j];
        float kv = kn[d0 + j];
        float qp = (dh < 32) ? -qn[d0 + j + 32] : qn[d0 + j - 32];
        float kp = (dh < 32) ? -kn[d0 + j + 32] : kn[d0 + j - 32];
        oq[j] = (qv * c + qp * s) * 0.125f;   // fold 1/sqrt(DH) exactly
        ok[j] = kv * c + kp * s;
    }
    size_t pb = ((size_t)(b * HH + h) * LL + l) * 32 + (dh0 >> 1);
    *(uint2*)(g_qf + pb) = make_uint2(h2pack(oq[0], oq[1]), h2pack(oq[2], oq[3]));
    *(uint2*)(g_kf + pb) = make_uint2(h2pack(ok[0], ok[1]), h2pack(ok[2], ok[3]));
}

// ---------------- kernel 4: flash attention (R14 structure) ----
#define AW 36
#define PL (64 * AW)                  // words per plane
#define ATTN_SMEM (5 * PL * 4)        // 46080 B: Q, K0, V0, K1, V1

__global__ __launch_bounds__(128, 4)
void attn_kernel(const int* __restrict__ seq_id) {
    extern __shared__ uint32_t smw[];
    uint32_t* Qf = smw;                 // [64][AW]
    uint32_t* Kf[2] = { smw + 1 * PL, smw + 3 * PL };
    uint32_t* Vf[2] = { smw + 2 * PL, smw + 4 * PL };
    __shared__ int kseq[2][64];

    const int bh = blockIdx.x, qt = blockIdx.y;
    const int b = bh >> 4, hh = bh & 15;
    const int tid = threadIdx.x;
    const int w = tid >> 5, lane = tid & 31;
    const int grp = lane >> 2, qd = lane & 3;

    const int qbase = b * LL + qt * 64;
    const int qmin = seq_id[qbase];
    const int qmax = seq_id[qbase + 63];

    const uint32_t sb = (uint32_t)__cvta_generic_to_shared(smw);
    const uint32_t sK[2] = { sb + 1 * PL * 4, sb + 3 * PL * 4 };
    const uint32_t sV[2] = { sb + 2 * PL * 4, sb + 4 * PL * 4 };

    // kept range [lo,hi]: contiguous because seq_id is sorted
    int lo = 32, hi = -1;
    for (int kt = 0; kt < 32; kt++) {
        int kmin = seq_id[b * LL + kt * 64];
        int kmax = seq_id[b * LL + kt * 64 + 63];
        if (kmax >= qmin && kmin <= qmax) { if (kt < lo) lo = kt; hi = kt; }
    }

    // stage Q
    {
        const size_t qrow = ((size_t)bh * LL + qt * 64) * 32;
        #pragma unroll
        for (int i = 0; i < 4; i++) {
            int idx = tid + i * 128;
            int r = idx >> 3, c = idx & 7;
            cp16(sb + (r * AW + c * 4) * 4, g_qf + qrow + r * 32 + c * 4);
        }
        cp_commit();
    }
    // stage K/V + kseq for tile lo into buffer 0
    {
        const size_t krow = ((size_t)bh * LL + lo * 64) * 32;
        const size_t vbase = ((size_t)bh * 32 + lo) * 64 * 32;
        #pragma unroll
        for (int i = 0; i < 4; i++) {
            int idx = tid + i * 128;
            int r = idx >> 3, c = idx & 7;
            cp16(sK[0] + (r * AW + c * 4) * 4, g_kf + krow + r * 32 + c * 4);
            cp16(sV[0] + (r * AW + c * 4) * 4, g_vtf + vbase + r * 32 + c * 4);
        }
        cp_commit();
        if (tid < 64) kseq[0][tid] = seq_id[b * LL + lo * 64 + tid];
    }

    const int row0 = w * 16 + grp, row1 = row0 + 8;
    const int qs0 = seq_id[qbase + row0];
    const int qs1 = seq_id[qbase + row1];

    float m0 = -1e30f, m1 = -1e30f, l0s = 0.f, l1s = 0.f;
    float O[8][4];
    #pragma unroll
    for (int dt = 0; dt < 8; dt++)
        #pragma unroll
        for (int q = 0; q < 4; q++) O[dt][q] = 0.f;

    for (int kt = lo; kt <= hi; kt++) {
        const int buf = (kt - lo) & 1;
        cp_wait_all();
        __syncthreads();

        if (kt < hi) {
            const int nb = buf ^ 1;
            const size_t krow = ((size_t)bh * LL + (kt + 1) * 64) * 32;
            const size_t vbase = ((size_t)bh * 32 + (kt + 1)) * 64 * 32;
            #pragma unroll
            for (int i = 0; i < 4; i++) {
                int idx = tid + i * 128;
                int r = idx >> 3, c = idx & 7;
                cp16(sK[nb] + (r * AW + c * 4) * 4, g_kf + krow + r * 32 + c * 4);
                cp16(sV[nb] + (r * AW + c * 4) * 4, g_vtf + vbase + r * 32 + c * 4);
            }
            cp_commit();
            if (tid < 64) kseq[nb][tid] = seq_id[b * LL + (kt + 1) * 64 + tid];
        }

        const uint32_t* Kb = Kf[buf];
        const uint32_t* Vb = Vf[buf];

        // ---- S = Q K^T ----
        float S[8][4];
        #pragma unroll
        for (int nt = 0; nt < 8; nt++)
            #pragma unroll
            for (int q = 0; q < 4; q++) S[nt][q] = 0.f;
        #pragma unroll
        for (int ks = 0; ks < 4; ks++) {
            int r0w = (w * 16 + grp) * AW, r1w = (w * 16 + grp + 8) * AW;
            int kw0 = ks * 8 + qd;
            uint32_t a0 = Qf[r0w + kw0],     a1 = Qf[r1w + kw0];
            uint32_t a2 = Qf[r0w + kw0 + 4], a3 = Qf[r1w + kw0 + 4];
            #pragma unroll
            for (int nt = 0; nt < 8; nt++) {
                int nw = (nt * 8 + grp) * AW;
                mma16816h(S[nt], a0, a1, a2, a3, Kb[nw + kw0], Kb[nw + kw0 + 4]);
            }
        }

        // ---- mask ----
        #pragma unroll
        for (int nt = 0; nt < 8; nt++) {
            int c0 = kseq[buf][nt * 8 + 2 * qd];
            int c1 = kseq[buf][nt * 8 + 2 * qd + 1];
            if (c0 != qs0) S[nt][0] = -1e30f;
            if (c1 != qs0) S[nt][1] = -1e30f;
            if (c0 != qs1) S[nt][2] = -1e30f;
            if (c1 != qs1) S[nt][3] = -1e30f;
        }

        // ---- online softmax ----
        float mx0 = -1e30f, mx1 = -1e30f;
        #pragma unroll
        for (int nt = 0; nt < 8; nt++) {
            mx0 = fmaxf(mx0, fmaxf(S[nt][0], S[nt][1]));
            mx1 = fmaxf(mx1, fmaxf(S[nt][2], S[nt][3]));
        }
        mx0 = fmaxf(mx0, __shfl_xor_sync(0xffffffffu, mx0, 1));
        mx0 = fmaxf(mx0, __shfl_xor_sync(0xffffffffu, mx0, 2));
        mx1 = fmaxf(mx1, __shfl_xor_sync(0xffffffffu, mx1, 1));
        mx1 = fmaxf(mx1, __shfl_xor_sync(0xffffffffu, mx1, 2));
        float mn0 = fmaxf(m0, mx0), mn1 = fmaxf(m1, mx1);
        float sc0 = __expf(m0 - mn0), sc1 = __expf(m1 - mn1);
        m0 = mn0; m1 = mn1;
        float s0 = 0.f, s1 = 0.f;
        #pragma unroll
        for (int nt = 0; nt < 8; nt++) {
            S[nt][0] = __expf(S[nt][0] - mn0);
            S[nt][1] = __expf(S[nt][1] - mn0);
            S[nt][2] = __expf(S[nt][2] - mn1);
            S[nt][3] = __expf(S[nt][3] - mn1);
            s0 += S[nt][0] + S[nt][1];
            s1 += S[nt][2] + S[nt][3];
        }
        s0 += __shfl_xor_sync(0xffffffffu, s0, 1);
        s0 += __shfl_xor_sync(0xffffffffu, s0, 2);
        s1 += __shfl_xor_sync(0xffffffffu, s1, 1);
        s1 += __shfl_xor_sync(0xffffffffu, s1, 2);
        l0s = l0s * sc0 + s0;
        l1s = l1s * sc1 + s1;
        #pragma unroll
        for (int dt = 0; dt < 8; dt++) {
            O[dt][0] *= sc0; O[dt][1] *= sc0;
            O[dt][2] *= sc1; O[dt][3] *= sc1;
        }

        // ---- O += P V: P straight from registers (fragment match) ----
        #pragma unroll
        for (int ks = 0; ks < 4; ks++) {
            uint32_t a0 = h2pack(S[2*ks][0],     S[2*ks][1]);
            uint32_t a1 = h2pack(S[2*ks][2],     S[2*ks][3]);
            uint32_t a2 = h2pack(S[2*ks + 1][0], S[2*ks + 1][1]);
            uint32_t a3 = h2pack(S[2*ks + 1][2], S[2*ks + 1][3]);
            int kw0 = ks * 8 + qd;
            #pragma unroll
            for (int dt = 0; dt < 8; dt++) {
                int dw = (dt * 8 + grp) * AW;
                mma16816h(O[dt], a0, a1, a2, a3, Vb[dw + kw0], Vb[dw + kw0 + 4]);
            }
        }
    }

    // epilogue: fp16 ctx words
    float inv0 = 1.0f / l0s, inv1 = 1.0f / l1s;
    const int t0 = b * LL + qt * 64 + row0;
    const int t1 = b * LL + qt * 64 + row1;
    #pragma unroll
    for (int dt = 0; dt < 8; dt++) {
        int c = hh * DHH + dt * 8 + 2 * qd;
        g_ctx16[(size_t)t0 * KW + (c >> 1)] =
            h2pack(O[dt][0] * inv0, O[dt][1] * inv0);
        g_ctx16[(size_t)t1 * KW + (c >> 1)] =
            h2pack(O[dt][2] * inv1, O[dt][3] * inv1);
    }
}

// ---------------- launch ----------------
extern "C" void kernel_launch(void* const* d_in, const int* in_sizes, int n_in,
                              void* d_out, int out_size) {
    const float* x     = (const float*)d_in[0];
    const int*   seq   = (const int*)  d_in[1];
    const float* ln1w  = (const float*)d_in[2];
    const float* ln1b  = (const float*)d_in[3];
    const float* wqkv  = (const float*)d_in[4];
    const float* qlnw  = (const float*)d_in[5];
    const float* klnw  = (const float*)d_in[6];
    const float* outw  = (const float*)d_in[7];
    float* out = (float*)d_out;

    void *phh, *pw16, *po16, *pctx16;
    cudaGetSymbolAddress(&phh, g_hh);
    cudaGetSymbolAddress(&pw16, g_wqkv16);
    cudaGetSymbolAddress(&po16, g_outw16);
    cudaGetSymbolAddress(&pctx16, g_ctx16);

    cudaFuncSetAttribute(gemm_mma_fp16, cudaFuncAttributeMaxDynamicSharedMemorySize, GEMM_SMEM);
    cudaFuncSetAttribute(attn_kernel, cudaFuncAttributeMaxDynamicSharedMemorySize, ATTN_SMEM);

    // 0) fused prologue: weight conversions + RoPE table
    prologue_kernel<<<WQKV_BLKS + OUTW_BLKS + TBL_BLKS, 256>>>(wqkv, outw);

    // 1) LN1 -> fp16 words
    ln1_kernel<<<TT, 256>>>(x, ln1w, ln1b);

    // 2) QKV GEMM; Q/K -> fp16 g_qk16, V -> transposed fp16 g_vtf
    gemm_mma_fp16<<<dim3(3 * DD / 128, TT / 128), 256, GEMM_SMEM>>>(
        (const uint32_t*)phh, (const uint32_t*)pw16, (float*)nullptr, 3 * DD, 1);

    // 3) QK LN + RoPE (table, fp16 input) -> fp16 planes
    qk_rope_kernel<<<TT, 256>>>(qlnw, klnw);

    // 4) attention (double buffer + P in registers)
    attn_kernel<<<dim3(NBH, LL / 64), 128, ATTN_SMEM>>>(seq);

    // 5) output projection
    gemm_mma_fp16<<<dim3(DD / 128, TT / 128), 256, GEMM_SMEM>>>(
        (const uint32_t*)pctx16, (const uint32_t*)po16, out, DD, 0);
}